// round 1
// baseline (speedup 1.0000x reference)
#include <cuda_runtime.h>

// Problem dims (fixed)
#define BB   64
#define TT   512
#define IDIM 256
#define HH   512
#define BTH  (BB*TT*HH)

// Recurrence config
#define NCTA 128
#define COLS 4          // HH / NCTA output columns per CTA

// ------------------------------ scratch ------------------------------------
__device__ float g_xb[TT*BB*HH];      // input projection, time-major [t][b][h]
__device__ float g_out0[BB*TT*HH];    // layer-0 output [b][t][h]
__device__ float g_Ht[2][HH*BB];      // ping-pong hidden state, transposed [h][b]
__device__ unsigned g_gen = 0;
__device__ unsigned g_count = 0;

// ------------------------------ grid barrier --------------------------------
__device__ __forceinline__ void grid_barrier(unsigned nb)
{
    __syncthreads();
    if (threadIdx.x == 0) {
        __threadfence();
        volatile unsigned* vg = &g_gen;
        unsigned cur = *vg;
        if (atomicAdd(&g_count, 1u) == nb - 1u) {
            g_count = 0u;
            __threadfence();
            *vg = cur + 1u;
        } else {
            while (*vg == cur) { }
            __threadfence();
        }
    }
    __syncthreads();
}

// ------------------------------ input GEMM ----------------------------------
// Y[t][b][n] = sum_k X[m=(b,t)][k] * W[n][k] + b1[n] + b2[n]
// X row-major [M=BB*TT, K], W [HH, K]. Tiles 64x64x16, 4x4 per thread.
#define SSTR 68   // smem row stride (floats); 68*4B = 272B = 16B-aligned, conflict-shifted

__global__ void __launch_bounds__(256) gemm_ih(
    const float* __restrict__ Xin,   // used if use_g0 == 0
    const float* __restrict__ W,
    const float* __restrict__ b1,
    const float* __restrict__ b2,
    int K, int use_g0)
{
    __shared__ float As[16 * SSTR];
    __shared__ float Bs[16 * SSTR];

    const float* X = use_g0 ? g_out0 : Xin;

    const int tid = threadIdx.x;
    const int tx  = tid & 15;       // n-quad
    const int ty  = tid >> 4;       // m-quad
    const int nb  = blockIdx.x;
    const int mb  = blockIdx.y;
    const int ar  = tid >> 2;       // staging row 0..63
    const int ac  = tid & 3;        // staging k-quad 0..3

    const float* Xrow = X + (size_t)(mb * 64 + ar) * K;
    const float* Wrow = W + (size_t)(nb * 64 + ar) * K;

    float acc[4][4];
#pragma unroll
    for (int i = 0; i < 4; i++)
#pragma unroll
        for (int j = 0; j < 4; j++) acc[i][j] = 0.f;

    for (int k0 = 0; k0 < K; k0 += 16) {
        float4 av = *reinterpret_cast<const float4*>(Xrow + k0 + ac * 4);
        float4 bv = *reinterpret_cast<const float4*>(Wrow + k0 + ac * 4);
        As[(ac * 4 + 0) * SSTR + ar] = av.x;
        As[(ac * 4 + 1) * SSTR + ar] = av.y;
        As[(ac * 4 + 2) * SSTR + ar] = av.z;
        As[(ac * 4 + 3) * SSTR + ar] = av.w;
        Bs[(ac * 4 + 0) * SSTR + ar] = bv.x;
        Bs[(ac * 4 + 1) * SSTR + ar] = bv.y;
        Bs[(ac * 4 + 2) * SSTR + ar] = bv.z;
        Bs[(ac * 4 + 3) * SSTR + ar] = bv.w;
        __syncthreads();

#pragma unroll
        for (int kk = 0; kk < 16; kk++) {
            float4 a4 = *reinterpret_cast<const float4*>(&As[kk * SSTR + ty * 4]);
            float4 b4 = *reinterpret_cast<const float4*>(&Bs[kk * SSTR + tx * 4]);
            float aa[4] = {a4.x, a4.y, a4.z, a4.w};
            float bb[4] = {b4.x, b4.y, b4.z, b4.w};
#pragma unroll
            for (int i = 0; i < 4; i++)
#pragma unroll
                for (int j = 0; j < 4; j++)
                    acc[i][j] += aa[i] * bb[j];
        }
        __syncthreads();
    }

    const int n0 = nb * 64 + tx * 4;
    float4 bias;
    bias.x = b1[n0 + 0] + b2[n0 + 0];
    bias.y = b1[n0 + 1] + b2[n0 + 1];
    bias.z = b1[n0 + 2] + b2[n0 + 2];
    bias.w = b1[n0 + 3] + b2[n0 + 3];

#pragma unroll
    for (int i = 0; i < 4; i++) {
        int m  = mb * 64 + ty * 4 + i;
        int b_ = m >> 9;            // / TT
        int t_ = m & (TT - 1);
        float4 o;
        o.x = acc[i][0] + bias.x;
        o.y = acc[i][1] + bias.y;
        o.z = acc[i][2] + bias.z;
        o.w = acc[i][3] + bias.w;
        *reinterpret_cast<float4*>(&g_xb[((size_t)t_ * BB + b_) * HH + n0]) = o;
    }
}

// ------------------------------ recurrence ----------------------------------
// h_{t} = tanh(xb[t] + h_{t-1} @ W_hh^T)
// 128 CTAs; CTA c owns output columns [4c, 4c+4). Weight slice (transposed) in smem.
// Hidden state transposed in gmem: Ht[h][b], ping-pong buffers, grid barrier/step.
// Threads: 256 = 16 batch-quads (bq) x 16 K-slices (ks, 32 hi each).
__global__ void __launch_bounds__(256, 1) rnn_rec(
    const float* __restrict__ Whh,   // [HH, HH]
    const float* __restrict__ h0,    // [BB, HH] initial state for this layer
    float* __restrict__ out_param,   // final layer: d_out (out1); else unused
    float* __restrict__ hn,          // [BB, HH]
    int use_g0out)                   // 1: write g_out0, 0: write out_param
{
    __shared__ float Wsm[HH * COLS];     // Wsm[hi*4 + j] = Whh[hob+j][hi]
    __shared__ float red[16 * 256];

    const int tid = threadIdx.x;
    const int hob = blockIdx.x * COLS;
    const int bq  = tid & 15;
    const int ks  = tid >> 4;

    float* outp = use_g0out ? g_out0 : out_param;

    // Load transposed weight slice (once).
    for (int idx = tid; idx < HH * COLS; idx += 256) {
        int j  = idx & 3;
        int hi = idx >> 2;
        Wsm[idx] = Whh[(size_t)(hob + j) * HH + hi];
    }
    // Init hidden state (parity 0), transposed.
    {
        int j = tid >> 6;       // 0..3
        int b = tid & 63;
        g_Ht[0][(hob + j) * BB + b] = h0[(size_t)b * HH + hob + j];
    }
    grid_barrier(NCTA);

    for (int t = 0; t < TT; ++t) {
        const float4* Hr = reinterpret_cast<const float4*>(g_Ht[t & 1]);

        float acc[4][4];
#pragma unroll
        for (int i = 0; i < 4; i++)
#pragma unroll
            for (int j = 0; j < 4; j++) acc[i][j] = 0.f;

        const int hi0 = ks * 32;
#pragma unroll 8
        for (int hi = hi0; hi < hi0 + 32; ++hi) {
            float4 h4 = __ldcg(&Hr[hi * (BB / 4) + bq]);   // 4 batches
            float4 w4 = *reinterpret_cast<const float4*>(&Wsm[hi * COLS]); // 4 cols
            float ha[4] = {h4.x, h4.y, h4.z, h4.w};
            float wa[4] = {w4.x, w4.y, w4.z, w4.w};
#pragma unroll
            for (int i = 0; i < 4; i++)
#pragma unroll
                for (int j = 0; j < 4; j++)
                    acc[i][j] += ha[i] * wa[j];
        }

        // K-split partials -> smem. red[ks][o], o = b*4 + j = bq*16 + i*4 + j
#pragma unroll
        for (int i = 0; i < 4; i++) {
            *reinterpret_cast<float4*>(&red[ks * 256 + bq * 16 + i * 4]) =
                make_float4(acc[i][0], acc[i][1], acc[i][2], acc[i][3]);
        }
        __syncthreads();

        // Reduce 16 partials, add input projection, tanh, write.
        {
            float s = 0.f;
#pragma unroll
            for (int k2 = 0; k2 < 16; k2++) s += red[k2 * 256 + tid];
            const int b  = tid >> 2;
            const int j  = tid & 3;
            const int ho = hob + j;
            float z = s + __ldg(&g_xb[((size_t)t * BB + b) * HH + ho]);
            float v = tanhf(z);
            g_Ht[(t + 1) & 1][ho * BB + b] = v;           // next-step state
            outp[((size_t)b * TT + t) * HH + ho] = v;     // layer output [b][t][h]
            if (t == TT - 1) hn[(size_t)b * HH + ho] = v;
        }
        grid_barrier(NCTA);   // includes __syncthreads (protects red reuse too)
    }
}

// ------------------------------ launch --------------------------------------
extern "C" void kernel_launch(void* const* d_in, const int* in_sizes, int n_in,
                              void* d_out, int out_size)
{
    const float* x    = (const float*)d_in[0];
    const float* h0   = (const float*)d_in[1];   // [2, B, H]
    const float* Wih0 = (const float*)d_in[2];
    const float* Whh0 = (const float*)d_in[3];
    const float* bih0 = (const float*)d_in[4];
    const float* bhh0 = (const float*)d_in[5];
    const float* Wih1 = (const float*)d_in[6];
    const float* Whh1 = (const float*)d_in[7];
    const float* bih1 = (const float*)d_in[8];
    const float* bhh1 = (const float*)d_in[9];

    float* out  = (float*)d_out;
    float* out1 = out;                       // [B,T,H]
    float* hn0  = out + (size_t)BTH;         // h_n[0]
    float* hn1  = hn0 + (size_t)BB * HH;     // h_n[1]

    dim3 ggrid(HH / 64, (BB * TT) / 64);     // (8, 512)

    // layer 0: xb = x @ Wih0^T + biases
    gemm_ih<<<ggrid, 256>>>(x, Wih0, bih0, bhh0, IDIM, 0);
    // layer 0 recurrence -> g_out0, hn0
    rnn_rec<<<NCTA, 256>>>(Whh0, h0, nullptr, hn0, 1);
    // layer 1: xb = out0 @ Wih1^T + biases
    gemm_ih<<<ggrid, 256>>>(nullptr, Wih1, bih1, bhh1, HH, 1);
    // layer 1 recurrence -> out1, hn1
    rnn_rec<<<NCTA, 256>>>(Whh1, h0 + (size_t)BB * HH, out1, hn1, 0);
}

// round 2
// speedup vs baseline: 1.4937x; 1.4937x over previous
#include <cuda_runtime.h>

// Problem dims (fixed)
#define BB   64
#define TT   512
#define IDIM 256
#define HH   512
#define BTH  (BB*TT*HH)

// Recurrence decomposition: 16 batch-groups x 8 column-groups = 128 CTAs
#define GB   16          // batch groups
#define GC   8           // column groups (CTAs per sync group)
#define BPG  4           // batches per group (64/16)
#define CPG  64          // columns per CTA  (512/8)
#define NCTA (GB*GC)

// ------------------------------ scratch ------------------------------------
__device__ float g_xb[TT*BB*HH];         // input projection, time-major [t][b][h]
__device__ float g_out0[BB*TT*HH];       // layer-0 output [b][t][h]
__device__ float g_Ht[2][GB][HH*BPG];    // ping-pong hidden state per group: [c*4+b]
__device__ unsigned g_count[GB];         // per-group arrival counters (monotonic per launch)

// ------------------------------ input GEMM ----------------------------------
// Y[t][b][n] = sum_k X[m=(b,t)][k] * W[n][k] + b1[n] + b2[n]
// X row-major [M=BB*TT, K], W [HH, K]. Tiles 64x64x16, 4x4 per thread.
#define SSTR 68   // smem row stride (floats)

__global__ void __launch_bounds__(256) gemm_ih(
    const float* __restrict__ Xin,   // used if use_g0 == 0
    const float* __restrict__ W,
    const float* __restrict__ b1,
    const float* __restrict__ b2,
    int K, int use_g0)
{
    __shared__ float As[16 * SSTR];
    __shared__ float Bs[16 * SSTR];

    const int tid = threadIdx.x;

    // zero the recurrence sync counters (this kernel always precedes rnn_rec)
    if (blockIdx.x == 0 && blockIdx.y == 0 && tid < GB) g_count[tid] = 0u;

    const float* X = use_g0 ? g_out0 : Xin;

    const int tx  = tid & 15;       // n-quad
    const int ty  = tid >> 4;       // m-quad
    const int nb  = blockIdx.x;
    const int mb  = blockIdx.y;
    const int ar  = tid >> 2;       // staging row 0..63
    const int ac  = tid & 3;        // staging k-quad 0..3

    const float* Xrow = X + (size_t)(mb * 64 + ar) * K;
    const float* Wrow = W + (size_t)(nb * 64 + ar) * K;

    float acc[4][4];
#pragma unroll
    for (int i = 0; i < 4; i++)
#pragma unroll
        for (int j = 0; j < 4; j++) acc[i][j] = 0.f;

    for (int k0 = 0; k0 < K; k0 += 16) {
        float4 av = *reinterpret_cast<const float4*>(Xrow + k0 + ac * 4);
        float4 bv = *reinterpret_cast<const float4*>(Wrow + k0 + ac * 4);
        As[(ac * 4 + 0) * SSTR + ar] = av.x;
        As[(ac * 4 + 1) * SSTR + ar] = av.y;
        As[(ac * 4 + 2) * SSTR + ar] = av.z;
        As[(ac * 4 + 3) * SSTR + ar] = av.w;
        Bs[(ac * 4 + 0) * SSTR + ar] = bv.x;
        Bs[(ac * 4 + 1) * SSTR + ar] = bv.y;
        Bs[(ac * 4 + 2) * SSTR + ar] = bv.z;
        Bs[(ac * 4 + 3) * SSTR + ar] = bv.w;
        __syncthreads();

#pragma unroll
        for (int kk = 0; kk < 16; kk++) {
            float4 a4 = *reinterpret_cast<const float4*>(&As[kk * SSTR + ty * 4]);
            float4 b4 = *reinterpret_cast<const float4*>(&Bs[kk * SSTR + tx * 4]);
            float aa[4] = {a4.x, a4.y, a4.z, a4.w};
            float bb[4] = {b4.x, b4.y, b4.z, b4.w};
#pragma unroll
            for (int i = 0; i < 4; i++)
#pragma unroll
                for (int j = 0; j < 4; j++)
                    acc[i][j] += aa[i] * bb[j];
        }
        __syncthreads();
    }

    const int n0 = nb * 64 + tx * 4;
    float4 bias;
    bias.x = b1[n0 + 0] + b2[n0 + 0];
    bias.y = b1[n0 + 1] + b2[n0 + 1];
    bias.z = b1[n0 + 2] + b2[n0 + 2];
    bias.w = b1[n0 + 3] + b2[n0 + 3];

#pragma unroll
    for (int i = 0; i < 4; i++) {
        int m  = mb * 64 + ty * 4 + i;
        int b_ = m >> 9;            // / TT
        int t_ = m & (TT - 1);
        float4 o;
        o.x = acc[i][0] + bias.x;
        o.y = acc[i][1] + bias.y;
        o.z = acc[i][2] + bias.z;
        o.w = acc[i][3] + bias.w;
        *reinterpret_cast<float4*>(&g_xb[((size_t)t_ * BB + b_) * HH + n0]) = o;
    }
}

// ------------------------------ recurrence ----------------------------------
// h_{t+1}[b,c] = tanh(xb[t][b][c] + sum_k h_t[b,k] * Whh[c,k])
// CTA (bg,cg): batches [4*bg,4*bg+4), columns [64*cg, 64*cg+64).
// Whh slice transposed+stationary in smem (128KB). Per-step: stage 8KB group
// hidden block into smem, 4x4 register-tiled FMA with 16-way K split,
// smem-reduce, tanh, write, per-group (8 CTA) release/acquire flag sync.
__global__ void __launch_bounds__(256, 1) rnn_rec(
    const float* __restrict__ Whh,   // [HH, HH]
    const float* __restrict__ h0,    // [BB, HH] initial state for this layer
    float* __restrict__ out_param,   // final layer: d_out (out1); else unused
    float* __restrict__ hn,          // [BB, HH]
    int use_g0out)                   // 1: write g_out0, 0: write out_param
{
    extern __shared__ float sm[];
    float*  Wt   = sm;                                        // [512][64] transposed
    float4* hs4  = reinterpret_cast<float4*>(sm + HH * CPG);  // [512] = [k][4 batches]
    float*  red  = sm + HH * CPG + HH * BPG;                  // [16][256]

    const int tid = threadIdx.x;
    const int bg  = blockIdx.x & (GB - 1);
    const int cg  = blockIdx.x >> 4;
    const int c0  = cg * CPG;
    const int b0  = bg * BPG;
    const int ks  = tid >> 4;       // K-slice 0..15 (32 k each)
    const int cq  = tid & 15;       // column quad 0..15
    const int ob  = tid >> 6;       // output batch 0..3
    const int oc  = tid & 63;       // output column 0..63

    float* outp = use_g0out ? g_out0 : out_param;
    unsigned* cptr = &g_count[bg];

    // Load W slice transposed: Wt[k][c] = Whh[c0+c][k]. Conflict-free stores.
    for (int idx = tid; idx < CPG * (HH / 4); idx += 256) {
        int c  = idx & (CPG - 1);
        int k4 = idx >> 6;          // 0..127
        float4 w = *reinterpret_cast<const float4*>(Whh + (size_t)(c0 + c) * HH + k4 * 4);
        Wt[(k4 * 4 + 0) * CPG + c] = w.x;
        Wt[(k4 * 4 + 1) * CPG + c] = w.y;
        Wt[(k4 * 4 + 2) * CPG + c] = w.z;
        Wt[(k4 * 4 + 3) * CPG + c] = w.w;
    }

    // Init hidden state (parity 0): one element per thread (256 = CPG*BPG).
    {
        int c = tid >> 2;           // 0..63
        int b = tid & 3;
        g_Ht[0][bg][(c0 + c) * BPG + b] = h0[(size_t)(b0 + b) * HH + c0 + c];
    }
    __syncthreads();
    if (tid == 0) {
        asm volatile("fence.acq_rel.gpu;" ::: "memory");
        atomicAdd(cptr, 1u);
    }

    for (int t = 0; t < TT; ++t) {
        // Prefetch input projection (independent of h) - hides DRAM under poll.
        float xbv = __ldcg(&g_xb[((size_t)t * BB + (b0 + ob)) * HH + c0 + oc]);

        // Wait for all 8 CTAs of this batch-group to finish the previous step.
        if (tid == 0) {
            const unsigned target = (unsigned)(GC * (t + 1));
            unsigned v;
            do {
                asm volatile("ld.acquire.gpu.global.u32 %0, [%1];"
                             : "=r"(v) : "l"(cptr) : "memory");
            } while ((int)(v - target) < 0);
        }
        __syncthreads();

        // Stage this group's hidden block (8KB) into smem.
        const float4* src = reinterpret_cast<const float4*>(&g_Ht[t & 1][bg][0]);
        hs4[tid]       = __ldcg(&src[tid]);
        hs4[tid + 256] = __ldcg(&src[tid + 256]);
        __syncthreads();

        // 4 batches x 4 cols register tile over a 32-wide K slice.
        float acc[4][4];
#pragma unroll
        for (int i = 0; i < 4; i++)
#pragma unroll
            for (int j = 0; j < 4; j++) acc[i][j] = 0.f;

        const int k0 = ks * 32;
#pragma unroll 8
        for (int k = k0; k < k0 + 32; ++k) {
            float4 h4 = hs4[k];                                          // 4 batches
            float4 w4 = *reinterpret_cast<const float4*>(&Wt[k * CPG + cq * 4]); // 4 cols
            float ha[4] = {h4.x, h4.y, h4.z, h4.w};
            float wa[4] = {w4.x, w4.y, w4.z, w4.w};
#pragma unroll
            for (int i = 0; i < 4; i++)
#pragma unroll
                for (int j = 0; j < 4; j++)
                    acc[i][j] += ha[i] * wa[j];
        }

        // K-split partials -> smem.
#pragma unroll
        for (int b = 0; b < 4; ++b)
            *reinterpret_cast<float4*>(&red[ks * 256 + b * 64 + cq * 4]) =
                make_float4(acc[b][0], acc[b][1], acc[b][2], acc[b][3]);
        __syncthreads();

        // Reduce, tanh, write.
        float s = 0.f;
#pragma unroll
        for (int k2 = 0; k2 < 16; ++k2) s += red[k2 * 256 + tid];

        float v = tanhf(s + xbv);

        g_Ht[(t + 1) & 1][bg][(c0 + oc) * BPG + ob] = v;              // next state
        outp[((size_t)(b0 + ob) * TT + t) * HH + c0 + oc] = v;        // [b][t][h]
        if (t == TT - 1) hn[(size_t)(b0 + ob) * HH + c0 + oc] = v;

        __syncthreads();   // all writes done before the release arrive
        if (tid == 0) {
            asm volatile("fence.acq_rel.gpu;" ::: "memory");
            atomicAdd(cptr, 1u);
        }
    }
}

// ------------------------------ launch --------------------------------------
extern "C" void kernel_launch(void* const* d_in, const int* in_sizes, int n_in,
                              void* d_out, int out_size)
{
    const float* x    = (const float*)d_in[0];
    const float* h0   = (const float*)d_in[1];   // [2, B, H]
    const float* Wih0 = (const float*)d_in[2];
    const float* Whh0 = (const float*)d_in[3];
    const float* bih0 = (const float*)d_in[4];
    const float* bhh0 = (const float*)d_in[5];
    const float* Wih1 = (const float*)d_in[6];
    const float* Whh1 = (const float*)d_in[7];
    const float* bih1 = (const float*)d_in[8];
    const float* bhh1 = (const float*)d_in[9];

    float* out  = (float*)d_out;
    float* out1 = out;                       // [B,T,H]
    float* hn0  = out + (size_t)BTH;         // h_n[0]
    float* hn1  = hn0 + (size_t)BB * HH;     // h_n[1]

    static int smem_set = 0;
    const int REC_SMEM = (HH * CPG + HH * BPG + 16 * 256) * 4;  // 155648 B
    if (!smem_set) {
        cudaFuncSetAttribute(rnn_rec, cudaFuncAttributeMaxDynamicSharedMemorySize, REC_SMEM);
        smem_set = 1;
    }

    dim3 ggrid(HH / 64, (BB * TT) / 64);     // (8, 512)

    // layer 0: xb = x @ Wih0^T + biases (also zeroes sync counters)
    gemm_ih<<<ggrid, 256>>>(x, Wih0, bih0, bhh0, IDIM, 0);
    // layer 0 recurrence -> g_out0, hn0
    rnn_rec<<<NCTA, 256, REC_SMEM>>>(Whh0, h0, nullptr, hn0, 1);
    // layer 1: xb = out0 @ Wih1^T + biases (re-zeroes sync counters)
    gemm_ih<<<ggrid, 256>>>(nullptr, Wih1, bih1, bhh1, HH, 1);
    // layer 1 recurrence -> out1, hn1
    rnn_rec<<<NCTA, 256, REC_SMEM>>>(Whh1, h0 + (size_t)BB * HH, out1, hn1, 0);
}

// round 3
// speedup vs baseline: 1.4986x; 1.0033x over previous
#include <cuda_runtime.h>
#include <cstdint>

// Problem dims (fixed)
#define BB   64
#define TT   512
#define IDIM 256
#define HH   512
#define BTH  (BB*TT*HH)

// Recurrence decomposition: 16 clusters (batch groups) x 8 CTAs (column groups)
#define GB   16
#define GC   8
#define BPG  4           // batches per group
#define CPG  64          // columns per CTA
#define NCTA (GB*GC)

// ------------------------------ scratch ------------------------------------
__device__ float g_xb[TT*BB*HH];      // input projection, time-major [t][b][h]
__device__ float g_out0[BB*TT*HH];    // layer-0 output [b][t][h]

// ------------------------------ input GEMM ----------------------------------
#define SSTR 68

__global__ void __launch_bounds__(256) gemm_ih(
    const float* __restrict__ Xin,
    const float* __restrict__ W,
    const float* __restrict__ b1,
    const float* __restrict__ b2,
    int K, int use_g0)
{
    __shared__ float As[16 * SSTR];
    __shared__ float Bs[16 * SSTR];

    const float* X = use_g0 ? g_out0 : Xin;

    const int tid = threadIdx.x;
    const int tx  = tid & 15;
    const int ty  = tid >> 4;
    const int nb  = blockIdx.x;
    const int mb  = blockIdx.y;
    const int ar  = tid >> 2;
    const int ac  = tid & 3;

    const float* Xrow = X + (size_t)(mb * 64 + ar) * K;
    const float* Wrow = W + (size_t)(nb * 64 + ar) * K;

    float acc[4][4];
#pragma unroll
    for (int i = 0; i < 4; i++)
#pragma unroll
        for (int j = 0; j < 4; j++) acc[i][j] = 0.f;

    for (int k0 = 0; k0 < K; k0 += 16) {
        float4 av = *reinterpret_cast<const float4*>(Xrow + k0 + ac * 4);
        float4 bv = *reinterpret_cast<const float4*>(Wrow + k0 + ac * 4);
        As[(ac * 4 + 0) * SSTR + ar] = av.x;
        As[(ac * 4 + 1) * SSTR + ar] = av.y;
        As[(ac * 4 + 2) * SSTR + ar] = av.z;
        As[(ac * 4 + 3) * SSTR + ar] = av.w;
        Bs[(ac * 4 + 0) * SSTR + ar] = bv.x;
        Bs[(ac * 4 + 1) * SSTR + ar] = bv.y;
        Bs[(ac * 4 + 2) * SSTR + ar] = bv.z;
        Bs[(ac * 4 + 3) * SSTR + ar] = bv.w;
        __syncthreads();

#pragma unroll
        for (int kk = 0; kk < 16; kk++) {
            float4 a4 = *reinterpret_cast<const float4*>(&As[kk * SSTR + ty * 4]);
            float4 b4 = *reinterpret_cast<const float4*>(&Bs[kk * SSTR + tx * 4]);
            float aa[4] = {a4.x, a4.y, a4.z, a4.w};
            float bb[4] = {b4.x, b4.y, b4.z, b4.w};
#pragma unroll
            for (int i = 0; i < 4; i++)
#pragma unroll
                for (int j = 0; j < 4; j++)
                    acc[i][j] += aa[i] * bb[j];
        }
        __syncthreads();
    }

    const int n0 = nb * 64 + tx * 4;
    float4 bias;
    bias.x = b1[n0 + 0] + b2[n0 + 0];
    bias.y = b1[n0 + 1] + b2[n0 + 1];
    bias.z = b1[n0 + 2] + b2[n0 + 2];
    bias.w = b1[n0 + 3] + b2[n0 + 3];

#pragma unroll
    for (int i = 0; i < 4; i++) {
        int m  = mb * 64 + ty * 4 + i;
        int b_ = m >> 9;
        int t_ = m & (TT - 1);
        float4 o;
        o.x = acc[i][0] + bias.x;
        o.y = acc[i][1] + bias.y;
        o.z = acc[i][2] + bias.z;
        o.w = acc[i][3] + bias.w;
        *reinterpret_cast<float4*>(&g_xb[((size_t)t_ * BB + b_) * HH + n0]) = o;
    }
}

// ------------------------------ cluster helpers -----------------------------
__device__ __forceinline__ uint32_t smem_u32(const void* p) {
    uint32_t a;
    asm("{ .reg .u64 t; cvta.to.shared.u64 t, %1; cvt.u32.u64 %0, t; }"
        : "=r"(a) : "l"(p));
    return a;
}

__device__ __forceinline__ void mbar_wait_cluster(uint32_t mbar, uint32_t parity) {
    asm volatile(
        "{\n\t"
        ".reg .pred P;\n\t"
        "WL%=:\n\t"
        "mbarrier.try_wait.parity.acquire.cluster.shared::cta.b64 P, [%0], %1;\n\t"
        "@!P bra WL%=;\n\t"
        "}"
        :: "r"(mbar), "r"(parity) : "memory");
}

// ------------------------------ recurrence ----------------------------------
// h_{t+1}[b,c] = tanh(xb[t][b][c] + sum_k h_t[b,k] * Whh[c,k])
// Cluster of 8 CTAs per batch group. Per CTA: 128KB W slice (transposed) +
// 2x8KB double-buffered group hidden state + 16KB reduce staging, all smem.
// State exchange: each thread st.async's its output value to all 8 CTAs'
// next-buffer; mbarrier expect_tx(8192B)/try_wait replaces all gmem sync.
//
// smem layout (dynamic): Wt[512*64] | hb[2][4*512] | red[16*256] | mbar[2]
#define SM_W    (HH*CPG)                 // 32768 floats
#define SM_HB   (SM_W)                   // + 2*2048
#define SM_RED  (SM_W + 2*BPG*HH)        // + 4096
#define SM_MBAR (SM_RED + 16*256)        // + 2 x u64
#define REC_SMEM_BYTES ((SM_MBAR + 8) * 4)

#define STEP_TX (GC * 256 * 4)           // 8192 bytes per phase

__global__ void __launch_bounds__(256, 1) __cluster_dims__(GC, 1, 1)
rnn_rec(const float* __restrict__ Whh,
        const float* __restrict__ h0,
        float* __restrict__ out_param,
        float* __restrict__ hn,
        int use_g0out)
{
    extern __shared__ float sm[];
    float* Wt  = sm;                 // [k][c]  k=0..511, c=0..63
    float* hb0 = sm + SM_HB;         // [b][k]  b=0..3, k=0..511
    float* hb1 = hb0 + BPG * HH;
    float* red = sm + SM_RED;        // [16][256]
    uint64_t* mbar = reinterpret_cast<uint64_t*>(sm + SM_MBAR);

    const int tid = threadIdx.x;
    uint32_t cg;
    asm("mov.u32 %0, %%cluster_ctarank;" : "=r"(cg));
    const int bg  = blockIdx.x >> 3;
    const int c0  = (int)cg * CPG;
    const int b0  = bg * BPG;
    const int ks  = tid >> 4;        // K-slice 0..15 (32 k each)
    const int cq  = tid & 15;        // column quad 0..15
    const int ob  = tid >> 6;        // output batch 0..3
    const int oc  = tid & 63;        // output column 0..63

    float* outp = use_g0out ? g_out0 : out_param;

    const uint32_t mbar_u0 = smem_u32(&mbar[0]);
    const uint32_t mbar_u1 = smem_u32(&mbar[1]);
    const uint32_t hb_u0   = smem_u32(hb0);
    const uint32_t hb_u1   = smem_u32(hb1);

    // Load W slice transposed: Wt[k][c] = Whh[c0+c][k].
    for (int idx = tid; idx < CPG * (HH / 4); idx += 256) {
        int c  = idx & (CPG - 1);
        int k4 = idx >> 6;
        float4 w = *reinterpret_cast<const float4*>(Whh + (size_t)(c0 + c) * HH + k4 * 4);
        Wt[(k4 * 4 + 0) * CPG + c] = w.x;
        Wt[(k4 * 4 + 1) * CPG + c] = w.y;
        Wt[(k4 * 4 + 2) * CPG + c] = w.z;
        Wt[(k4 * 4 + 3) * CPG + c] = w.w;
    }
    // Init hidden state buffer 0: hb0[b][k] = h0[b0+b][k]; 512 float4 loads.
    {
        float4* d = reinterpret_cast<float4*>(hb0);
        const float4* s = reinterpret_cast<const float4*>(h0 + (size_t)b0 * HH);
        d[tid]       = s[tid];
        d[tid + 256] = s[tid + 256];
    }
    // mbarriers: arrive count 1 (the expect_tx arrive); pre-post both phases.
    if (tid == 0) {
        asm volatile("mbarrier.init.shared.b64 [%0], %1;" :: "r"(mbar_u0), "r"(1u) : "memory");
        asm volatile("mbarrier.init.shared.b64 [%0], %1;" :: "r"(mbar_u1), "r"(1u) : "memory");
        asm volatile("mbarrier.arrive.expect_tx.shared.b64 _, [%0], %1;"
                     :: "r"(mbar_u0), "r"((unsigned)STEP_TX) : "memory");
        asm volatile("mbarrier.arrive.expect_tx.shared.b64 _, [%0], %1;"
                     :: "r"(mbar_u1), "r"((unsigned)STEP_TX) : "memory");
    }
    __syncthreads();
    // Cluster-wide: mbarrier init + W/h loads visible before any st.async.
    asm volatile("barrier.cluster.arrive.aligned;" ::: "memory");
    asm volatile("barrier.cluster.wait.aligned;"   ::: "memory");

    uint32_t ph0 = 0, ph1 = 0;
    const uint32_t my_off = (uint32_t)((ob * HH + c0 + oc) * 4);  // byte offset in hb

    for (int t = 0; t < TT; ++t) {
        const int p = t & 1;
        // Prefetch input projection (independent of h).
        float xbv = __ldcg(&g_xb[((size_t)t * BB + (b0 + ob)) * HH + c0 + oc]);

        // Wait for this step's state (t=0 is pre-loaded locally).
        if (t > 0) {
            if (p) { mbar_wait_cluster(mbar_u1, ph1); ph1 ^= 1; }
            else   { mbar_wait_cluster(mbar_u0, ph0); ph0 ^= 1; }
            if (tid == 0) {   // re-arm this mbar for its next use (t+2)
                uint32_t mu = p ? mbar_u1 : mbar_u0;
                asm volatile("mbarrier.arrive.expect_tx.shared.b64 _, [%0], %1;"
                             :: "r"(mu), "r"((unsigned)STEP_TX) : "memory");
            }
        }

        const float* hb = p ? hb1 : hb0;

        // 4 batches x 4 cols register tile over this thread's 32-k slice.
        float acc[4][4];
#pragma unroll
        for (int i = 0; i < 4; i++)
#pragma unroll
            for (int j = 0; j < 4; j++) acc[i][j] = 0.f;

        const int kb = ks * 32;
#pragma unroll
        for (int kc = 0; kc < 32; kc += 4) {
            const int k = kb + kc;
            float4 hv[4];
#pragma unroll
            for (int b = 0; b < 4; b++)
                hv[b] = *reinterpret_cast<const float4*>(&hb[b * HH + k]);
#pragma unroll
            for (int kk = 0; kk < 4; kk++) {
                float4 w4 = *reinterpret_cast<const float4*>(&Wt[(k + kk) * CPG + cq * 4]);
                float wj[4] = {w4.x, w4.y, w4.z, w4.w};
                float hk[4] = {hv[0].x, hv[1].x, hv[2].x, hv[3].x};
                if (kk == 1) { hk[0]=hv[0].y; hk[1]=hv[1].y; hk[2]=hv[2].y; hk[3]=hv[3].y; }
                if (kk == 2) { hk[0]=hv[0].z; hk[1]=hv[1].z; hk[2]=hv[2].z; hk[3]=hv[3].z; }
                if (kk == 3) { hk[0]=hv[0].w; hk[1]=hv[1].w; hk[2]=hv[2].w; hk[3]=hv[3].w; }
#pragma unroll
                for (int b = 0; b < 4; b++)
#pragma unroll
                    for (int j = 0; j < 4; j++)
                        acc[b][j] += hk[b] * wj[j];
            }
        }

        // K-split partials -> smem: red[ks][b*64 + cq*4 + j]
#pragma unroll
        for (int b = 0; b < 4; ++b)
            *reinterpret_cast<float4*>(&red[ks * 256 + b * 64 + cq * 4]) =
                make_float4(acc[b][0], acc[b][1], acc[b][2], acc[b][3]);
        __syncthreads();

        // Reduce 16 partials, add xb, tanh.
        float s = 0.f;
#pragma unroll
        for (int k2 = 0; k2 < 16; ++k2) s += red[k2 * 256 + tid];
        float v = tanhf(s + xbv);

        // Outputs to gmem (no ordering needed).
        outp[((size_t)(b0 + ob) * TT + t) * HH + c0 + oc] = v;
        if (t == TT - 1) hn[(size_t)(b0 + ob) * HH + c0 + oc] = v;

        // Push next state to all 8 cluster CTAs' other buffer + their mbar.
        if (t < TT - 1) {
            const uint32_t dst_l  = (p ? hb_u0 : hb_u1) + my_off;
            const uint32_t mbar_l = p ? mbar_u0 : mbar_u1;
            const uint32_t vb = __float_as_uint(v);
#pragma unroll
            for (int r = 0; r < GC; r++) {
                uint32_t da, ma;
                asm("mapa.shared::cluster.u32 %0, %1, %2;" : "=r"(da) : "r"(dst_l),  "r"(r));
                asm("mapa.shared::cluster.u32 %0, %1, %2;" : "=r"(ma) : "r"(mbar_l), "r"(r));
                asm volatile(
                    "st.async.shared::cluster.mbarrier::complete_tx::bytes.b32 [%0], %1, [%2];"
                    :: "r"(da), "r"(vb), "r"(ma) : "memory");
            }
        }
        __syncthreads();   // red reuse next step (cheap; waits are the real gate)
    }

    // Safety: no CTA leaves while peers could still touch its smem.
    asm volatile("barrier.cluster.arrive.aligned;" ::: "memory");
    asm volatile("barrier.cluster.wait.aligned;"   ::: "memory");
}

// ------------------------------ launch --------------------------------------
extern "C" void kernel_launch(void* const* d_in, const int* in_sizes, int n_in,
                              void* d_out, int out_size)
{
    const float* x    = (const float*)d_in[0];
    const float* h0   = (const float*)d_in[1];   // [2, B, H]
    const float* Wih0 = (const float*)d_in[2];
    const float* Whh0 = (const float*)d_in[3];
    const float* bih0 = (const float*)d_in[4];
    const float* bhh0 = (const float*)d_in[5];
    const float* Wih1 = (const float*)d_in[6];
    const float* Whh1 = (const float*)d_in[7];
    const float* bih1 = (const float*)d_in[8];
    const float* bhh1 = (const float*)d_in[9];

    float* out  = (float*)d_out;
    float* out1 = out;                       // [B,T,H]
    float* hn0  = out + (size_t)BTH;         // h_n[0]
    float* hn1  = hn0 + (size_t)BB * HH;     // h_n[1]

    static int smem_set = 0;
    if (!smem_set) {
        cudaFuncSetAttribute(rnn_rec, cudaFuncAttributeMaxDynamicSharedMemorySize,
                             REC_SMEM_BYTES);
        smem_set = 1;
    }

    dim3 ggrid(HH / 64, (BB * TT) / 64);     // (8, 512)

    gemm_ih<<<ggrid, 256>>>(x, Wih0, bih0, bhh0, IDIM, 0);
    rnn_rec<<<NCTA, 256, REC_SMEM_BYTES>>>(Whh0, h0, nullptr, hn0, 1);
    gemm_ih<<<ggrid, 256>>>(nullptr, Wih1, bih1, bhh1, HH, 1);
    rnn_rec<<<NCTA, 256, REC_SMEM_BYTES>>>(Whh1, h0 + (size_t)BB * HH, out1, hn1, 0);
}